// round 15
// baseline (speedup 1.0000x reference)
#include <cuda_runtime.h>
#include <cuda_bf16.h>
#include <cuda_fp16.h>
#include <stdint.h>

#define DEV_INLINE __device__ __forceinline__

constexpr int BB = 8, S = 2048, DM = 768, DH = 64;
constexpr int BSROWS = BB * S;

// ---------------- scratch ----------------
__device__ __nv_bfloat16 g_Q[BSROWS * DH];
__device__ __nv_bfloat16 g_K[BSROWS * DH];
__device__ __half g_Vt[BB * DH * S];                 // [b][d][s], f16
__device__ __nv_bfloat16 g_Wt[3 * DH * DM];          // [which][dv][k]
__device__ float g_WvtF[DH * DM];                    // fp32 Wv transposed [d][k]
__device__ float g_part4[128 * 4 * DM];
__device__ float g_xsum[BB * DM];

// ---------------- helpers ----------------
DEV_INLINE void mma16816(float* d, const uint32_t* a, const uint32_t* b) {
    asm volatile(
        "mma.sync.aligned.m16n8k16.row.col.f32.bf16.bf16.f32 "
        "{%0,%1,%2,%3}, {%4,%5,%6,%7}, {%8,%9}, {%0,%1,%2,%3};\n"
        : "+f"(d[0]), "+f"(d[1]), "+f"(d[2]), "+f"(d[3])
        : "r"(a[0]), "r"(a[1]), "r"(a[2]), "r"(a[3]), "r"(b[0]), "r"(b[1]));
}
DEV_INLINE void mma16816h(float* d, const uint32_t* a, const uint32_t* b) {
    asm volatile(
        "mma.sync.aligned.m16n8k16.row.col.f32.f16.f16.f32 "
        "{%0,%1,%2,%3}, {%4,%5,%6,%7}, {%8,%9}, {%0,%1,%2,%3};\n"
        : "+f"(d[0]), "+f"(d[1]), "+f"(d[2]), "+f"(d[3])
        : "r"(a[0]), "r"(a[1]), "r"(a[2]), "r"(a[3]), "r"(b[0]), "r"(b[1]));
}
DEV_INLINE void ldsm_x4(uint32_t* r, const void* p) {
    uint32_t a = (uint32_t)__cvta_generic_to_shared(p);
    asm volatile("ldmatrix.sync.aligned.m8n8.x4.shared.b16 {%0,%1,%2,%3}, [%4];\n"
                 : "=r"(r[0]), "=r"(r[1]), "=r"(r[2]), "=r"(r[3]) : "r"(a));
}
DEV_INLINE uint32_t packbf2(float a, float b) {
    __nv_bfloat162 h = __floats2bfloat162_rn(a, b);
    return *reinterpret_cast<uint32_t*>(&h);
}
DEV_INLINE uint32_t packh2(float a, float b) {
    __half2 h = __floats2half2_rn(a, b);
    return *reinterpret_cast<uint32_t*>(&h);
}
DEV_INLINE uint32_t ex2h2(float s0, float s1) {
    uint32_t h;
    asm volatile("cvt.rn.f16x2.f32 %0, %1, %2;\n" : "=r"(h) : "f"(s1), "f"(s0));
    asm volatile("ex2.approx.f16x2 %0, %0;\n" : "+r"(h));
    return h;
}
DEV_INLINE float2 h2f2(uint32_t u) {
    __half2 hh = *reinterpret_cast<__half2*>(&u);
    return __half22float2(hh);
}
DEV_INLINE void cp_async16(void* smem, const void* gmem) {
    uint32_t s = (uint32_t)__cvta_generic_to_shared(smem);
    asm volatile("cp.async.cg.shared.global [%0], [%1], 16;\n" :: "r"(s), "l"(gmem));
}
DEV_INLINE void cp_commit() { asm volatile("cp.async.commit_group;\n"); }
template<int N> DEV_INLINE void cp_wait() { asm volatile("cp.async.wait_group %0;\n" :: "n"(N)); }
DEV_INLINE void wg_bar(int id) { asm volatile("bar.sync %0, 128;\n" :: "r"(id)); }

// ---------------- kernel 1: weight prep ----------------
__global__ void prep_wt_kernel(const float* __restrict__ Wq,
                               const float* __restrict__ Wk,
                               const float* __restrict__ Wv) {
    int i = blockIdx.x * blockDim.x + threadIdx.x;
    if (i >= 3 * DH * DM) return;
    int which = i / (DH * DM);
    int r = i % (DH * DM);
    int dv = r / DM, k = r % DM;
    const float* W = (which == 0) ? Wq : (which == 1) ? Wk : Wv;
    float val = W[k * DH + dv];
    g_Wt[i] = __float2bfloat16(val);
    if (which == 2) g_WvtF[r] = val;
}

// ---------------- projection GEMM body (4-stage pipeline) ----------------
template<int NT>
DEV_INLINE void proj_body(const float* __restrict__ X, int woff,
                          const float* __restrict__ bias0, const float* __restrict__ bias1,
                          float scale, int do_xsum, int blk, char* smraw) {
    float (*Xs)[128][68] = (float(*)[128][68])smraw;                        // 4 stages
    __nv_bfloat16 (*Ws)[NT * 8][72] =
        (__nv_bfloat16(*)[NT * 8][72])(smraw + 4 * 128 * 68 * 4);           // 4 stages

    const int tid = threadIdx.x;
    const int w = tid >> 5, l = tid & 31, g = l >> 2, t4 = l & 3;
    const int rowbase = blk * 128;
    const __nv_bfloat16* Wt = g_Wt + woff;

    auto load_stage = [&](int kc, int stg) {
#pragma unroll
        for (int i = 0; i < 8; i++) {
            int e = tid + i * 256; int row = e >> 4, c4 = e & 15;
            cp_async16(&Xs[stg][row][c4 * 4],
                       X + (size_t)(rowbase + row) * DM + kc * 64 + c4 * 4);
        }
#pragma unroll
        for (int i = 0; i < NT / 4; i++) {
            int e = tid + i * 256; int row = e >> 3, c8 = e & 7;
            cp_async16(&Ws[stg][row][c8 * 8],
                       Wt + (size_t)row * DM + kc * 64 + c8 * 8);
        }
        cp_commit();
    };

    float acc[NT][4];
#pragma unroll
    for (int nt = 0; nt < NT; nt++)
#pragma unroll
        for (int j = 0; j < 4; j++) acc[nt][j] = 0.f;

    load_stage(0, 0);
    load_stage(1, 1);
    load_stage(2, 2);

    for (int kc = 0; kc < 12; kc++) {
        const int st = kc & 3;
        if (kc <= 9)       cp_wait<2>();
        else if (kc == 10) cp_wait<1>();
        else               cp_wait<0>();
        __syncthreads();                       // single leading barrier per chunk
        if (kc + 3 < 12) load_stage(kc + 3, (kc + 3) & 3);

        if (do_xsum) {
            const int q = tid >> 6, c = tid & 63;
            float s = 0.f;
#pragma unroll 8
            for (int r = 0; r < 32; r++) s += Xs[st][q * 32 + r][c];
            g_part4[((size_t)blk * 4 + q) * DM + kc * 64 + c] = s;
        }

        uint32_t a[4][4];
#pragma unroll
        for (int kt = 0; kt < 4; kt++) {
            int r0 = w * 16 + g, c0 = kt * 16 + 2 * t4;
            a[kt][0] = packbf2(Xs[st][r0][c0],         Xs[st][r0][c0 + 1]);
            a[kt][1] = packbf2(Xs[st][r0 + 8][c0],     Xs[st][r0 + 8][c0 + 1]);
            a[kt][2] = packbf2(Xs[st][r0][c0 + 8],     Xs[st][r0][c0 + 9]);
            a[kt][3] = packbf2(Xs[st][r0 + 8][c0 + 8], Xs[st][r0 + 8][c0 + 9]);
        }
#pragma unroll
        for (int nt = 0; nt < NT; nt++) {
#pragma unroll
            for (int kt = 0; kt < 4; kt++) {
                uint32_t bfr[2];
                int rn = nt * 8 + g, ck = kt * 16 + 2 * t4;
                bfr[0] = *(const uint32_t*)&Ws[st][rn][ck];
                bfr[1] = *(const uint32_t*)&Ws[st][rn][ck + 8];
                mma16816(acc[nt], a[kt], bfr);
            }
        }
    }

    const int r0 = rowbase + w * 16 + g;
    if (NT == 8) {
        // Q epilogue: scale = (1/8)*log2(e) so attention scores are log2-domain
#pragma unroll
        for (int nt = 0; nt < NT; nt++) {
            int c = nt * 8 + 2 * t4;
            float b0 = bias0[c], b1 = bias0[c + 1];
            *(uint32_t*)(g_Q + (size_t)r0 * DH + c) =
                packbf2((acc[nt][0] + b0) * scale, (acc[nt][1] + b1) * scale);
            *(uint32_t*)(g_Q + (size_t)(r0 + 8) * DH + c) =
                packbf2((acc[nt][2] + b0) * scale, (acc[nt][3] + b1) * scale);
        }
    } else {
#pragma unroll
        for (int nt = 0; nt < 8; nt++) {
            int c = nt * 8 + 2 * t4;
            float b0 = bias0[c], b1 = bias0[c + 1];
            *(uint32_t*)(g_K + (size_t)r0 * DH + c) =
                packbf2(acc[nt][0] + b0, acc[nt][1] + b1);
            *(uint32_t*)(g_K + (size_t)(r0 + 8) * DH + c) =
                packbf2(acc[nt][2] + b0, acc[nt][3] + b1);
        }
        // V staged to smem as f16 [s][d] (Ws[0] region, free after last chunk),
        // then transposed coalesced to g_Vt
        __half (*Vsm)[72] = (__half(*)[72])&Ws[0][0][0];
        __syncthreads();
#pragma unroll
        for (int nt = 8; nt < 16; nt++) {
            int c = (nt - 8) * 8 + 2 * t4;
            float b0 = bias1[c], b1 = bias1[c + 1];
            *(uint32_t*)&Vsm[w * 16 + g][c]     = packh2(acc[nt][0] + b0, acc[nt][1] + b1);
            *(uint32_t*)&Vsm[w * 16 + g + 8][c] = packh2(acc[nt][2] + b0, acc[nt][3] + b1);
        }
        __syncthreads();
        const int b = rowbase >> 11, s0 = rowbase & 2047;
        const int d = tid >> 2, part = tid & 3;
#pragma unroll
        for (int jj = 0; jj < 4; jj++) {
            __half tmp[8];
#pragma unroll
            for (int m = 0; m < 8; m++) tmp[m] = Vsm[part * 32 + jj * 8 + m][d];
            *(uint4*)(g_Vt + ((size_t)(b * DH + d)) * S + s0 + part * 32 + jj * 8) =
                *(uint4*)tmp;
        }
    }
}

__global__ __launch_bounds__(256) void proj_fused_kernel(
    const float* __restrict__ x1, const float* __restrict__ x2,
    const float* __restrict__ bq, const float* __restrict__ bk,
    const float* __restrict__ bv) {
    extern __shared__ char smraw[];
    if (blockIdx.x < 128)
        proj_body<16>(x2, DH * DM, bk, bv, 1.0f, 1, blockIdx.x, smraw);
    else
        proj_body<8>(x1, 0, bq, bq, 0.18033688011112042f, 0, blockIdx.x - 128, smraw);
}

// ---------------- combine x2 partials (96 blocks) ----------------
__global__ __launch_bounds__(256) void xsum_combine_kernel() {
    __shared__ float red[4][64];
    const int sub = threadIdx.x >> 6, ol = threadIdx.x & 63;
    const int o = blockIdx.x * 64 + ol;
    const int b = o / DM, c = o % DM;
    float a = 0.f;
#pragma unroll
    for (int i = 0; i < 16; i++)
        a += g_part4[(size_t)(b * 64 + sub * 16 + i) * DM + c];
    red[sub][ol] = a;
    __syncthreads();
    if (sub == 0)
        g_xsum[o] = red[0][ol] + red[1][ol] + red[2][ol] + red[3][ol];
}

// ---------------- flash attention (R12: 128-row, split-K WGs, LDSM frags) ---
constexpr int SMATT = 4 * 64 * 72 * 2 * 2 + 192 * 4;   // 74496

__global__ __launch_bounds__(256) void attn_kernel(const float* __restrict__ bv,
                                                   const float* __restrict__ gamma,
                                                   const float* __restrict__ beta,
                                                   float* __restrict__ out) {
    extern __shared__ char sm[];
    __nv_bfloat16 (*Kb4)[64][72] = (__nv_bfloat16(*)[64][72])sm;
    __half (*Vb4)[64][72] = (__half(*)[64][72])(sm + 36864);
    float* cs = (float*)(sm + 73728);

    const int qt = blockIdx.x, b = blockIdx.y;
    const int tid = threadIdx.x;
    const int w = tid >> 5, l = tid & 31, g = l >> 2, t4 = l & 3;
    const int l7 = l & 7, l3 = l >> 3;
    const int wg = w >> 2, ww = w & 3;
    const int wt128 = tid & 127;

    // Q staging via cp.async (in flight while computing c below)
    __nv_bfloat16 (*Qs)[72] = (__nv_bfloat16(*)[72])sm;
    const __nv_bfloat16* Qp = g_Q + ((size_t)b * S + qt * 128) * DH;
#pragma unroll
    for (int i = 0; i < 4; i++) {
        int e = tid + i * 256; int row = e >> 3, c8 = e & 7;
        cp_async16(&Qs[row][c8 * 8], Qp + (size_t)row * DH + c8 * 8);
    }
    cp_commit();

    // c[d] = dot(xsum[b], WvtF[d]) + 2048*bv[d]
    {
        const float* xs = g_xsum + b * DM;
#pragma unroll
        for (int dd = 0; dd < 8; dd++) {
            const int d = w * 8 + dd;
            const float* wt = g_WvtF + (size_t)d * DM;
            float acc = 0.f;
#pragma unroll
            for (int i = 0; i < DM / 32; i++) {
                int j = l + i * 32;
                acc += xs[j] * wt[j];
            }
#pragma unroll
            for (int off = 16; off; off >>= 1) acc += __shfl_xor_sync(0xffffffffu, acc, off);
            if (l == 0) cs[d] = acc + 2048.0f * bv[d];
        }
    }
    if (tid < 64)        cs[64 + tid]  = gamma[tid];
    else if (tid < 128)  cs[128 + tid - 64] = beta[tid - 64];
    cp_wait<0>();
    __syncthreads();

    uint32_t aq[2][4][4];
#pragma unroll
    for (int mt = 0; mt < 2; mt++) {
        int r0 = ww * 32 + mt * 16 + g;
#pragma unroll
        for (int kt = 0; kt < 4; kt++) {
            int c0 = kt * 16 + 2 * t4;
            aq[mt][kt][0] = *(const uint32_t*)&Qs[r0][c0];
            aq[mt][kt][1] = *(const uint32_t*)&Qs[r0 + 8][c0];
            aq[mt][kt][2] = *(const uint32_t*)&Qs[r0][c0 + 8];
            aq[mt][kt][3] = *(const uint32_t*)&Qs[r0 + 8][c0 + 8];
        }
    }
    __syncthreads();

    const __nv_bfloat16* Kbase = g_K  + (size_t)b * S * DH;
    const __half*        Vtb   = g_Vt + (size_t)b * DH * S;

    {
        int tau = wg;
#pragma unroll
        for (int i = 0; i < 4; i++) {
            int e = wt128 + i * 128; int row = e >> 3, c8 = e & 7;
            cp_async16(&Kb4[wg * 2][row][c8 * 8],
                       Kbase + (size_t)(tau * 64 + row) * DH + c8 * 8);
        }
#pragma unroll
        for (int i = 0; i < 4; i++) {
            int e = wt128 + i * 128; int row = e >> 3, c8 = e & 7;
            cp_async16(&Vb4[wg * 2][row][c8 * 8],
                       Vtb + (size_t)row * S + tau * 64 + c8 * 8);
        }
        cp_commit();
    }

    float o[2][8][4];
#pragma unroll
    for (int mt = 0; mt < 2; mt++)
#pragma unroll
        for (int nv = 0; nv < 8; nv++)
#pragma unroll
            for (int j = 0; j < 4; j++) o[mt][nv][j] = 0.f;
    float ls[2][2] = {{0.f, 0.f}, {0.f, 0.f}};

    for (int t = 0; t < 16; t++) {
        const int st = t & 1, bi = wg * 2 + st;
        if (t + 1 < 16) {
            int tau = 2 * (t + 1) + wg, b2 = wg * 2 + (st ^ 1);
#pragma unroll
            for (int i = 0; i < 4; i++) {
                int e = wt128 + i * 128; int row = e >> 3, c8 = e & 7;
                cp_async16(&Kb4[b2][row][c8 * 8],
                           Kbase + (size_t)(tau * 64 + row) * DH + c8 * 8);
            }
#pragma unroll
            for (int i = 0; i < 4; i++) {
                int e = wt128 + i * 128; int row = e >> 3, c8 = e & 7;
                cp_async16(&Vb4[b2][row][c8 * 8],
                           Vtb + (size_t)row * S + tau * 64 + c8 * 8);
            }
            cp_commit();
            cp_wait<1>();
        } else {
            cp_wait<0>();
        }
        wg_bar(wg + 1);

        const __nv_bfloat16 (*Kst)[72] = Kb4[bi];
        const __half (*Vst)[72] = Vb4[bi];

        // Two half-iterations: nt 0-3 -> PV k2 0-1; nt 4-7 -> PV k2 2-3.
#pragma unroll
        for (int ph = 0; ph < 2; ph++) {
            uint32_t pa[2][2][4];   // [mt][k2local][reg]
#pragma unroll
            for (int ntl = 0; ntl < 4; ntl++) {
                const int nt = ph * 4 + ntl;
                uint32_t b0[4], b1[4];
                ldsm_x4(b0, &Kst[nt * 8 + l7][l3 * 8]);
                ldsm_x4(b1, &Kst[nt * 8 + l7][32 + l3 * 8]);
#pragma unroll
                for (int mt = 0; mt < 2; mt++) {
                    float sc4[4] = {0.f, 0.f, 0.f, 0.f};
                    mma16816(sc4, aq[mt][0], b0 + 0);
                    mma16816(sc4, aq[mt][1], b0 + 2);
                    mma16816(sc4, aq[mt][2], b1 + 0);
                    mma16816(sc4, aq[mt][3], b1 + 2);
                    uint32_t ph01 = ex2h2(sc4[0], sc4[1]);
                    uint32_t ph23 = ex2h2(sc4[2], sc4[3]);
                    float2 f01 = h2f2(ph01), f23 = h2f2(ph23);
                    ls[mt][0] += f01.x + f01.y;
                    ls[mt][1] += f23.x + f23.y;
                    pa[mt][ntl >> 1][(ntl & 1) * 2 + 0] = ph01;
                    pa[mt][ntl >> 1][(ntl & 1) * 2 + 1] = ph23;
                }
            }
#pragma unroll
            for (int nv = 0; nv < 8; nv++) {
                uint32_t vf[4];
                ldsm_x4(vf, &Vst[nv * 8 + l7][ph * 32 + l3 * 8]);
#pragma unroll
                for (int mt = 0; mt < 2; mt++) {
                    mma16816h(o[mt][nv], pa[mt][0], vf + 0);
                    mma16816h(o[mt][nv], pa[mt][1], vf + 2);
                }
            }
        }
        wg_bar(wg + 1);
    }

    // cross-WG combine
    __syncthreads();
    float* ex = (float*)sm;
    if (wg == 1) {
        float* dst = ex + ww * 2176;
#pragma unroll
        for (int mt = 0; mt < 2; mt++)
#pragma unroll
            for (int nv = 0; nv < 8; nv++)
#pragma unroll
                for (int j = 0; j < 4; j++)
                    dst[((mt * 8 + nv) * 4 + j) * 32 + l] = o[mt][nv][j];
#pragma unroll
        for (int mt = 0; mt < 2; mt++)
#pragma unroll
            for (int h = 0; h < 2; h++)
                dst[2048 + (mt * 2 + h) * 32 + l] = ls[mt][h];
    }
    __syncthreads();
    if (wg == 0) {
        const float* src = ex + ww * 2176;
#pragma unroll
        for (int mt = 0; mt < 2; mt++)
#pragma unroll
            for (int nv = 0; nv < 8; nv++)
#pragma unroll
                for (int j = 0; j < 4; j++)
                    o[mt][nv][j] += src[((mt * 8 + nv) * 4 + j) * 32 + l];
#pragma unroll
        for (int mt = 0; mt < 2; mt++)
#pragma unroll
            for (int h = 0; h < 2; h++) {
                float v = ls[mt][h] + src[2048 + (mt * 2 + h) * 32 + l];
                v += __shfl_xor_sync(0xffffffffu, v, 1);
                v += __shfl_xor_sync(0xffffffffu, v, 2);
                ls[mt][h] = v;
            }

        const float* gs = cs + 64;
        const float* bs = cs + 128;
        const float isc = 1.f / 2047.f;
#pragma unroll
        for (int mt = 0; mt < 2; mt++) {
            const float inv0 = 1.f / ls[mt][0];
            const float inv1 = 1.f / ls[mt][1];
            float s1a = 0.f, s2a = 0.f, s1b = 0.f, s2b = 0.f;
#pragma unroll
            for (int nv = 0; nv < 8; nv++) {
                int c = nv * 8 + 2 * t4;
                float cc0 = cs[c], cc1 = cs[c + 1];
                float x0 = (cc0 - o[mt][nv][0] * inv0) * isc;
                float x1 = (cc1 - o[mt][nv][1] * inv0) * isc;
                float y0 = (cc0 - o[mt][nv][2] * inv1) * isc;
                float y1 = (cc1 - o[mt][nv][3] * inv1) * isc;
                s1a += x0 + x1; s2a += x0 * x0 + x1 * x1;
                s1b += y0 + y1; s2b += y0 * y0 + y1 * y1;
                o[mt][nv][0] = x0; o[mt][nv][1] = x1;
                o[mt][nv][2] = y0; o[mt][nv][3] = y1;
            }
#pragma unroll
            for (int off = 1; off <= 2; off <<= 1) {
                s1a += __shfl_xor_sync(0xffffffffu, s1a, off);
                s2a += __shfl_xor_sync(0xffffffffu, s2a, off);
                s1b += __shfl_xor_sync(0xffffffffu, s1b, off);
                s2b += __shfl_xor_sync(0xffffffffu, s2b, off);
            }
            float mu0 = s1a * (1.f / 64.f), var0 = s2a * (1.f / 64.f) - mu0 * mu0;
            float mu1 = s1b * (1.f / 64.f), var1 = s2b * (1.f / 64.f) - mu1 * mu1;
            float r0f = rsqrtf(var0 + 1e-5f);
            float r1f = rsqrtf(var1 + 1e-5f);

            const int row0 = b * S + qt * 128 + ww * 32 + mt * 16 + g;
#pragma unroll
            for (int nv = 0; nv < 8; nv++) {
                int c = nv * 8 + 2 * t4;
                float ga0 = gs[c], ga1 = gs[c + 1], be0 = bs[c], be1 = bs[c + 1];
                *(float2*)(out + (size_t)row0 * DH + c) =
                    make_float2((o[mt][nv][0] - mu0) * r0f * ga0 + be0,
                                (o[mt][nv][1] - mu0) * r0f * ga1 + be1);
                *(float2*)(out + (size_t)(row0 + 8) * DH + c) =
                    make_float2((o[mt][nv][2] - mu1) * r1f * ga0 + be0,
                                (o[mt][nv][3] - mu1) * r1f * ga1 + be1);
            }
        }
    }
}

// ---------------- launch ----------------
extern "C" void kernel_launch(void* const* d_in, const int* in_sizes, int n_in,
                              void* d_out, int out_size) {
    const float* x1 = (const float*)d_in[0];
    const float* x2 = (const float*)d_in[1];
    const float* Wq = (const float*)d_in[2];
    const float* bq = (const float*)d_in[3];
    const float* Wk = (const float*)d_in[4];
    const float* bk = (const float*)d_in[5];
    const float* Wv = (const float*)d_in[6];
    const float* bv = (const float*)d_in[7];
    const float* gamma = (const float*)d_in[8];
    const float* beta  = (const float*)d_in[9];
    float* out = (float*)d_out;

    const int SM16 = 4 * 128 * 68 * 4 + 4 * 128 * 72 * 2;   // 212992
    cudaFuncSetAttribute(proj_fused_kernel, cudaFuncAttributeMaxDynamicSharedMemorySize, SM16);
    cudaFuncSetAttribute(attn_kernel, cudaFuncAttributeMaxDynamicSharedMemorySize, SMATT);

    prep_wt_kernel<<<(3 * DH * DM + 255) / 256, 256>>>(Wq, Wk, Wv);
    proj_fused_kernel<<<256, 256, SM16>>>(x1, x2, bq, bk, bv);
    xsum_combine_kernel<<<96, 256>>>();
    attn_kernel<<<dim3(16, BB), 256, SMATT>>>(bv, gamma, beta, out);
}

// round 17
// speedup vs baseline: 1.0480x; 1.0480x over previous
#include <cuda_runtime.h>
#include <cuda_bf16.h>
#include <cuda_fp16.h>
#include <stdint.h>

#define DEV_INLINE __device__ __forceinline__

constexpr int BB = 8, S = 2048, DM = 768, DH = 64;
constexpr int BSROWS = BB * S;

// ---------------- scratch ----------------
__device__ __nv_bfloat16 g_Q[BSROWS * DH];
__device__ __nv_bfloat16 g_K[BSROWS * DH];
__device__ __half g_Vt[BB * DH * S];                 // [b][d][s], f16
__device__ __nv_bfloat16 g_Wt[3 * DH * DM];          // [which][dv][k]
__device__ float g_WvtF[DH * DM];                    // fp32 Wv transposed [d][k]
__device__ float g_part4[128 * 4 * DM];
__device__ float g_xsum[BB * DM];

// ---------------- helpers ----------------
DEV_INLINE void mma16816(float* d, const uint32_t* a, const uint32_t* b) {
    asm volatile(
        "mma.sync.aligned.m16n8k16.row.col.f32.bf16.bf16.f32 "
        "{%0,%1,%2,%3}, {%4,%5,%6,%7}, {%8,%9}, {%0,%1,%2,%3};\n"
        : "+f"(d[0]), "+f"(d[1]), "+f"(d[2]), "+f"(d[3])
        : "r"(a[0]), "r"(a[1]), "r"(a[2]), "r"(a[3]), "r"(b[0]), "r"(b[1]));
}
DEV_INLINE void mma16816h(float* d, const uint32_t* a, const uint32_t* b) {
    asm volatile(
        "mma.sync.aligned.m16n8k16.row.col.f32.f16.f16.f32 "
        "{%0,%1,%2,%3}, {%4,%5,%6,%7}, {%8,%9}, {%0,%1,%2,%3};\n"
        : "+f"(d[0]), "+f"(d[1]), "+f"(d[2]), "+f"(d[3])
        : "r"(a[0]), "r"(a[1]), "r"(a[2]), "r"(a[3]), "r"(b[0]), "r"(b[1]));
}
DEV_INLINE void ldsm_x4(uint32_t* r, const void* p) {
    uint32_t a = (uint32_t)__cvta_generic_to_shared(p);
    asm volatile("ldmatrix.sync.aligned.m8n8.x4.shared.b16 {%0,%1,%2,%3}, [%4];\n"
                 : "=r"(r[0]), "=r"(r[1]), "=r"(r[2]), "=r"(r[3]) : "r"(a));
}
DEV_INLINE uint32_t packbf2(float a, float b) {
    __nv_bfloat162 h = __floats2bfloat162_rn(a, b);
    return *reinterpret_cast<uint32_t*>(&h);
}
DEV_INLINE uint32_t packh2(float a, float b) {
    __half2 h = __floats2half2_rn(a, b);
    return *reinterpret_cast<uint32_t*>(&h);
}
DEV_INLINE uint32_t ex2h2(float s0, float s1) {
    uint32_t h;
    asm volatile("cvt.rn.f16x2.f32 %0, %1, %2;\n" : "=r"(h) : "f"(s1), "f"(s0));
    asm volatile("ex2.approx.f16x2 %0, %0;\n" : "+r"(h));
    return h;
}
DEV_INLINE float2 h2f2(uint32_t u) {
    __half2 hh = *reinterpret_cast<__half2*>(&u);
    return __half22float2(hh);
}
DEV_INLINE void cp_async16(void* smem, const void* gmem) {
    uint32_t s = (uint32_t)__cvta_generic_to_shared(smem);
    asm volatile("cp.async.cg.shared.global [%0], [%1], 16;\n" :: "r"(s), "l"(gmem));
}
DEV_INLINE void cp_commit() { asm volatile("cp.async.commit_group;\n"); }
template<int N> DEV_INLINE void cp_wait() { asm volatile("cp.async.wait_group %0;\n" :: "n"(N)); }
DEV_INLINE void wg_bar(int id) { asm volatile("bar.sync %0, 128;\n" :: "r"(id)); }

// ---------------- kernel 1: weight prep ----------------
__global__ void prep_wt_kernel(const float* __restrict__ Wq,
                               const float* __restrict__ Wk,
                               const float* __restrict__ Wv) {
    int i = blockIdx.x * blockDim.x + threadIdx.x;
    if (i >= 3 * DH * DM) return;
    int which = i / (DH * DM);
    int r = i % (DH * DM);
    int dv = r / DM, k = r % DM;
    const float* W = (which == 0) ? Wq : (which == 1) ? Wk : Wv;
    float val = W[k * DH + dv];
    g_Wt[i] = __float2bfloat16(val);
    if (which == 2) g_WvtF[r] = val;
}

// ---------------- projection GEMM body (2-stage, R9/R12 config) -------------
template<int NT>
DEV_INLINE void proj_body(const float* __restrict__ X, int woff,
                          const float* __restrict__ bias0, const float* __restrict__ bias1,
                          float scale, int do_xsum, int blk, char* smraw) {
    float (*Xs)[128][68] = (float(*)[128][68])smraw;
    __nv_bfloat16 (*Ws)[NT * 8][72] =
        (__nv_bfloat16(*)[NT * 8][72])(smraw + 2 * 128 * 68 * 4);

    const int tid = threadIdx.x;
    const int w = tid >> 5, l = tid & 31, g = l >> 2, t4 = l & 3;
    const int rowbase = blk * 128;
    const __nv_bfloat16* Wt = g_Wt + woff;

    float acc[NT][4];
#pragma unroll
    for (int nt = 0; nt < NT; nt++)
#pragma unroll
        for (int j = 0; j < 4; j++) acc[nt][j] = 0.f;

    {
#pragma unroll
        for (int i = 0; i < 8; i++) {
            int e = tid + i * 256; int row = e >> 4, c4 = e & 15;
            cp_async16(&Xs[0][row][c4 * 4], X + (size_t)(rowbase + row) * DM + c4 * 4);
        }
#pragma unroll
        for (int i = 0; i < NT / 4; i++) {
            int e = tid + i * 256; int row = e >> 3, c8 = e & 7;
            cp_async16(&Ws[0][row][c8 * 8], Wt + (size_t)row * DM + c8 * 8);
        }
        cp_commit();
    }

    for (int kc = 0; kc < 12; kc++) {
        const int st = kc & 1;
        if (kc + 1 < 12) {
#pragma unroll
            for (int i = 0; i < 8; i++) {
                int e = tid + i * 256; int row = e >> 4, c4 = e & 15;
                cp_async16(&Xs[st ^ 1][row][c4 * 4],
                           X + (size_t)(rowbase + row) * DM + (kc + 1) * 64 + c4 * 4);
            }
#pragma unroll
            for (int i = 0; i < NT / 4; i++) {
                int e = tid + i * 256; int row = e >> 3, c8 = e & 7;
                cp_async16(&Ws[st ^ 1][row][c8 * 8],
                           Wt + (size_t)row * DM + (kc + 1) * 64 + c8 * 8);
            }
            cp_commit();
            cp_wait<1>();
        } else {
            cp_wait<0>();
        }
        __syncthreads();

        if (do_xsum) {
            const int q = tid >> 6, c = tid & 63;
            float s = 0.f;
#pragma unroll 8
            for (int r = 0; r < 32; r++) s += Xs[st][q * 32 + r][c];
            g_part4[((size_t)blk * 4 + q) * DM + kc * 64 + c] = s;
        }

        uint32_t a[4][4];
#pragma unroll
        for (int kt = 0; kt < 4; kt++) {
            int r0 = w * 16 + g, c0 = kt * 16 + 2 * t4;
            a[kt][0] = packbf2(Xs[st][r0][c0],         Xs[st][r0][c0 + 1]);
            a[kt][1] = packbf2(Xs[st][r0 + 8][c0],     Xs[st][r0 + 8][c0 + 1]);
            a[kt][2] = packbf2(Xs[st][r0][c0 + 8],     Xs[st][r0][c0 + 9]);
            a[kt][3] = packbf2(Xs[st][r0 + 8][c0 + 8], Xs[st][r0 + 8][c0 + 9]);
        }
#pragma unroll
        for (int nt = 0; nt < NT; nt++) {
#pragma unroll
            for (int kt = 0; kt < 4; kt++) {
                uint32_t bfr[2];
                int rn = nt * 8 + g, ck = kt * 16 + 2 * t4;
                bfr[0] = *(const uint32_t*)&Ws[st][rn][ck];
                bfr[1] = *(const uint32_t*)&Ws[st][rn][ck + 8];
                mma16816(acc[nt], a[kt], bfr);
            }
        }
        __syncthreads();
    }

    const int r0 = rowbase + w * 16 + g;
    if (NT == 8) {
        // Q epilogue: scale = (1/8)*log2(e) so attention scores are log2-domain
#pragma unroll
        for (int nt = 0; nt < NT; nt++) {
            int c = nt * 8 + 2 * t4;
            float b0 = bias0[c], b1 = bias0[c + 1];
            *(uint32_t*)(g_Q + (size_t)r0 * DH + c) =
                packbf2((acc[nt][0] + b0) * scale, (acc[nt][1] + b1) * scale);
            *(uint32_t*)(g_Q + (size_t)(r0 + 8) * DH + c) =
                packbf2((acc[nt][2] + b0) * scale, (acc[nt][3] + b1) * scale);
        }
    } else {
#pragma unroll
        for (int nt = 0; nt < 8; nt++) {
            int c = nt * 8 + 2 * t4;
            float b0 = bias0[c], b1 = bias0[c + 1];
            *(uint32_t*)(g_K + (size_t)r0 * DH + c) =
                packbf2(acc[nt][0] + b0, acc[nt][1] + b1);
            *(uint32_t*)(g_K + (size_t)(r0 + 8) * DH + c) =
                packbf2(acc[nt][2] + b0, acc[nt][3] + b1);
        }
        // V staged to smem as f16 [s][d], then transposed coalesced to g_Vt
        __half (*Vsm)[72] = (__half(*)[72])&Ws[0][0][0];
#pragma unroll
        for (int nt = 8; nt < 16; nt++) {
            int c = (nt - 8) * 8 + 2 * t4;
            float b0 = bias1[c], b1 = bias1[c + 1];
            *(uint32_t*)&Vsm[w * 16 + g][c]     = packh2(acc[nt][0] + b0, acc[nt][1] + b1);
            *(uint32_t*)&Vsm[w * 16 + g + 8][c] = packh2(acc[nt][2] + b0, acc[nt][3] + b1);
        }
        __syncthreads();
        const int b = rowbase >> 11, s0 = rowbase & 2047;
        const int d = tid >> 2, part = tid & 3;
#pragma unroll
        for (int jj = 0; jj < 4; jj++) {
            __half tmp[8];
#pragma unroll
            for (int m = 0; m < 8; m++) tmp[m] = Vsm[part * 32 + jj * 8 + m][d];
            *(uint4*)(g_Vt + ((size_t)(b * DH + d)) * S + s0 + part * 32 + jj * 8) =
                *(uint4*)tmp;
        }
    }
}

__global__ __launch_bounds__(256) void proj_fused_kernel(
    const float* __restrict__ x1, const float* __restrict__ x2,
    const float* __restrict__ bq, const float* __restrict__ bk,
    const float* __restrict__ bv) {
    extern __shared__ char smraw[];
    if (blockIdx.x < 128)
        proj_body<16>(x2, DH * DM, bk, bv, 1.0f, 1, blockIdx.x, smraw);
    else
        proj_body<8>(x1, 0, bq, bq, 0.18033688011112042f, 0, blockIdx.x - 128, smraw);
}

// ---------------- combine x2 partials (96 blocks) ----------------
__global__ __launch_bounds__(256) void xsum_combine_kernel() {
    __shared__ float red[4][64];
    const int sub = threadIdx.x >> 6, ol = threadIdx.x & 63;
    const int o = blockIdx.x * 64 + ol;
    const int b = o / DM, c = o % DM;
    float a = 0.f;
#pragma unroll
    for (int i = 0; i < 16; i++)
        a += g_part4[(size_t)(b * 64 + sub * 16 + i) * DM + c];
    red[sub][ol] = a;
    __syncthreads();
    if (sub == 0)
        g_xsum[o] = red[0][ol] + red[1][ol] + red[2][ol] + red[3][ol];
}

// ---------------- flash attention (R12 + correct single-barrier loop) -------
// per iter: cp_wait (my tile-t writes done) -> wg_bar (all writes visible,
// all warps past iter t-1) -> prefetch t+1 into st^1 (safe) -> compute t.
constexpr int SMATT = 4 * 64 * 72 * 2 * 2 + 192 * 4;   // 74496

__global__ __launch_bounds__(256) void attn_kernel(const float* __restrict__ bv,
                                                   const float* __restrict__ gamma,
                                                   const float* __restrict__ beta,
                                                   float* __restrict__ out) {
    extern __shared__ char sm[];
    __nv_bfloat16 (*Kb4)[64][72] = (__nv_bfloat16(*)[64][72])sm;
    __half (*Vb4)[64][72] = (__half(*)[64][72])(sm + 36864);
    float* cs = (float*)(sm + 73728);

    const int qt = blockIdx.x, b = blockIdx.y;
    const int tid = threadIdx.x;
    const int w = tid >> 5, l = tid & 31, g = l >> 2, t4 = l & 3;
    const int l7 = l & 7, l3 = l >> 3;
    const int wg = w >> 2, ww = w & 3;
    const int wt128 = tid & 127;

    // Q staging via cp.async (in flight while computing c below)
    __nv_bfloat16 (*Qs)[72] = (__nv_bfloat16(*)[72])sm;
    const __nv_bfloat16* Qp = g_Q + ((size_t)b * S + qt * 128) * DH;
#pragma unroll
    for (int i = 0; i < 4; i++) {
        int e = tid + i * 256; int row = e >> 3, c8 = e & 7;
        cp_async16(&Qs[row][c8 * 8], Qp + (size_t)row * DH + c8 * 8);
    }
    cp_commit();

    // c[d] = dot(xsum[b], WvtF[d]) + 2048*bv[d]
    {
        const float* xs = g_xsum + b * DM;
#pragma unroll
        for (int dd = 0; dd < 8; dd++) {
            const int d = w * 8 + dd;
            const float* wt = g_WvtF + (size_t)d * DM;
            float acc = 0.f;
#pragma unroll
            for (int i = 0; i < DM / 32; i++) {
                int j = l + i * 32;
                acc += xs[j] * wt[j];
            }
#pragma unroll
            for (int off = 16; off; off >>= 1) acc += __shfl_xor_sync(0xffffffffu, acc, off);
            if (l == 0) cs[d] = acc + 2048.0f * bv[d];
        }
    }
    if (tid < 64)        cs[64 + tid]  = gamma[tid];
    else if (tid < 128)  cs[128 + tid - 64] = beta[tid - 64];
    cp_wait<0>();
    __syncthreads();

    uint32_t aq[2][4][4];
#pragma unroll
    for (int mt = 0; mt < 2; mt++) {
        int r0 = ww * 32 + mt * 16 + g;
#pragma unroll
        for (int kt = 0; kt < 4; kt++) {
            int c0 = kt * 16 + 2 * t4;
            aq[mt][kt][0] = *(const uint32_t*)&Qs[r0][c0];
            aq[mt][kt][1] = *(const uint32_t*)&Qs[r0 + 8][c0];
            aq[mt][kt][2] = *(const uint32_t*)&Qs[r0][c0 + 8];
            aq[mt][kt][3] = *(const uint32_t*)&Qs[r0 + 8][c0 + 8];
        }
    }
    __syncthreads();

    const __nv_bfloat16* Kbase = g_K  + (size_t)b * S * DH;
    const __half*        Vtb   = g_Vt + (size_t)b * DH * S;

    // prologue: tile 0 for this warpgroup
    {
        int tau = wg;
#pragma unroll
        for (int i = 0; i < 4; i++) {
            int e = wt128 + i * 128; int row = e >> 3, c8 = e & 7;
            cp_async16(&Kb4[wg * 2][row][c8 * 8],
                       Kbase + (size_t)(tau * 64 + row) * DH + c8 * 8);
        }
#pragma unroll
        for (int i = 0; i < 4; i++) {
            int e = wt128 + i * 128; int row = e >> 3, c8 = e & 7;
            cp_async16(&Vb4[wg * 2][row][c8 * 8],
                       Vtb + (size_t)row * S + tau * 64 + c8 * 8);
        }
        cp_commit();
    }

    float o[2][8][4];
#pragma unroll
    for (int mt = 0; mt < 2; mt++)
#pragma unroll
        for (int nv = 0; nv < 8; nv++)
#pragma unroll
            for (int j = 0; j < 4; j++) o[mt][nv][j] = 0.f;
    float ls[2][2] = {{0.f, 0.f}, {0.f, 0.f}};

    for (int t = 0; t < 16; t++) {
        const int st = t & 1, bi = wg * 2 + st;

        cp_wait<0>();        // my writes for tile t (sole pending group) done
        wg_bar(wg + 1);      // all warps' tile-t writes visible; all past t-1

        if (t + 1 < 16) {    // prefetch tile t+1 into st^1 (last read at t-1)
            int tau = 2 * (t + 1) + wg, b2 = wg * 2 + (st ^ 1);
#pragma unroll
            for (int i = 0; i < 4; i++) {
                int e = wt128 + i * 128; int row = e >> 3, c8 = e & 7;
                cp_async16(&Kb4[b2][row][c8 * 8],
                           Kbase + (size_t)(tau * 64 + row) * DH + c8 * 8);
            }
#pragma unroll
            for (int i = 0; i < 4; i++) {
                int e = wt128 + i * 128; int row = e >> 3, c8 = e & 7;
                cp_async16(&Vb4[b2][row][c8 * 8],
                           Vtb + (size_t)row * S + tau * 64 + c8 * 8);
            }
            cp_commit();
        }

        const __nv_bfloat16 (*Kst)[72] = Kb4[bi];
        const __half (*Vst)[72] = Vb4[bi];

        // Two half-iterations: nt 0-3 -> PV k2 0-1; nt 4-7 -> PV k2 2-3.
#pragma unroll
        for (int ph = 0; ph < 2; ph++) {
            uint32_t pa[2][2][4];   // [mt][k2local][reg]
#pragma unroll
            for (int ntl = 0; ntl < 4; ntl++) {
                const int nt = ph * 4 + ntl;
                uint32_t b0[4], b1[4];
                ldsm_x4(b0, &Kst[nt * 8 + l7][l3 * 8]);
                ldsm_x4(b1, &Kst[nt * 8 + l7][32 + l3 * 8]);
#pragma unroll
                for (int mt = 0; mt < 2; mt++) {
                    float sc4[4] = {0.f, 0.f, 0.f, 0.f};
                    mma16816(sc4, aq[mt][0], b0 + 0);
                    mma16816(sc4, aq[mt][1], b0 + 2);
                    mma16816(sc4, aq[mt][2], b1 + 0);
                    mma16816(sc4, aq[mt][3], b1 + 2);
                    uint32_t ph01 = ex2h2(sc4[0], sc4[1]);
                    uint32_t ph23 = ex2h2(sc4[2], sc4[3]);
                    float2 f01 = h2f2(ph01), f23 = h2f2(ph23);
                    ls[mt][0] += f01.x + f01.y;
                    ls[mt][1] += f23.x + f23.y;
                    pa[mt][ntl >> 1][(ntl & 1) * 2 + 0] = ph01;
                    pa[mt][ntl >> 1][(ntl & 1) * 2 + 1] = ph23;
                }
            }
#pragma unroll
            for (int nv = 0; nv < 8; nv++) {
                uint32_t vf[4];
                ldsm_x4(vf, &Vst[nv * 8 + l7][ph * 32 + l3 * 8]);
#pragma unroll
                for (int mt = 0; mt < 2; mt++) {
                    mma16816h(o[mt][nv], pa[mt][0], vf + 0);
                    mma16816h(o[mt][nv], pa[mt][1], vf + 2);
                }
            }
        }
    }

    // cross-WG combine
    __syncthreads();
    float* ex = (float*)sm;
    if (wg == 1) {
        float* dst = ex + ww * 2176;
#pragma unroll
        for (int mt = 0; mt < 2; mt++)
#pragma unroll
            for (int nv = 0; nv < 8; nv++)
#pragma unroll
                for (int j = 0; j < 4; j++)
                    dst[((mt * 8 + nv) * 4 + j) * 32 + l] = o[mt][nv][j];
#pragma unroll
        for (int mt = 0; mt < 2; mt++)
#pragma unroll
            for (int h = 0; h < 2; h++)
                dst[2048 + (mt * 2 + h) * 32 + l] = ls[mt][h];
    }
    __syncthreads();
    if (wg == 0) {
        const float* src = ex + ww * 2176;
#pragma unroll
        for (int mt = 0; mt < 2; mt++)
#pragma unroll
            for (int nv = 0; nv < 8; nv++)
#pragma unroll
                for (int j = 0; j < 4; j++)
                    o[mt][nv][j] += src[((mt * 8 + nv) * 4 + j) * 32 + l];
#pragma unroll
        for (int mt = 0; mt < 2; mt++)
#pragma unroll
            for (int h = 0; h < 2; h++) {
                float v = ls[mt][h] + src[2048 + (mt * 2 + h) * 32 + l];
                v += __shfl_xor_sync(0xffffffffu, v, 1);
                v += __shfl_xor_sync(0xffffffffu, v, 2);
                ls[mt][h] = v;
            }

        const float* gs = cs + 64;
        const float* bs = cs + 128;
        const float isc = 1.f / 2047.f;
#pragma unroll
        for (int mt = 0; mt < 2; mt++) {
            const float inv0 = 1.f / ls[mt][0];
            const float inv1 = 1.f / ls[mt][1];
            float s1a = 0.f, s2a = 0.f, s1b = 0.f, s2b = 0.f;
#pragma unroll
            for (int nv = 0; nv < 8; nv++) {
                int c = nv * 8 + 2 * t4;
                float cc0 = cs[c], cc1 = cs[c + 1];
                float x0 = (cc0 - o[mt][nv][0] * inv0) * isc;
                float x1 = (cc1 - o[mt][nv][1] * inv0) * isc;
                float y0 = (cc0 - o[mt][nv][2] * inv1) * isc;
                float y1 = (cc1 - o[mt][nv][3] * inv1) * isc;
                s1a += x0 + x1; s2a += x0 * x0 + x1 * x1;
                s1b += y0 + y1; s2b += y0 * y0 + y1 * y1;
                o[mt][nv][0] = x0; o[mt][nv][1] = x1;
                o[mt][nv][2] = y0; o[mt][nv][3] = y1;
            }
#pragma unroll
            for (int off = 1; off <= 2; off <<= 1) {
                s1a += __shfl_xor_sync(0xffffffffu, s1a, off);
                s2a += __shfl_xor_sync(0xffffffffu, s2a, off);
                s1b += __shfl_xor_sync(0xffffffffu, s1b, off);
                s2b += __shfl_xor_sync(0xffffffffu, s2b, off);
            }
            float mu0 = s1a * (1.f / 64.f), var0 = s2a * (1.f / 64.f) - mu0 * mu0;
            float mu1 = s1b * (1.f / 64.f), var1 = s2b * (1.f / 64.f) - mu1 * mu1;
            float r0f = rsqrtf(var0 + 1e-5f);
            float r1f = rsqrtf(var1 + 1e-5f);

            const int row0 = b * S + qt * 128 + ww * 32 + mt * 16 + g;
#pragma unroll
            for (int nv = 0; nv < 8; nv++) {
                int c = nv * 8 + 2 * t4;
                float ga0 = gs[c], ga1 = gs[c + 1], be0 = bs[c], be1 = bs[c + 1];
                *(float2*)(out + (size_t)row0 * DH + c) =
                    make_float2((o[mt][nv][0] - mu0) * r0f * ga0 + be0,
                                (o[mt][nv][1] - mu0) * r0f * ga1 + be1);
                *(float2*)(out + (size_t)(row0 + 8) * DH + c) =
                    make_float2((o[mt][nv][2] - mu1) * r1f * ga0 + be0,
                                (o[mt][nv][3] - mu1) * r1f * ga1 + be1);
            }
        }
    }
}

// ---------------- launch ----------------
extern "C" void kernel_launch(void* const* d_in, const int* in_sizes, int n_in,
                              void* d_out, int out_size) {
    const float* x1 = (const float*)d_in[0];
    const float* x2 = (const float*)d_in[1];
    const float* Wq = (const float*)d_in[2];
    const float* bq = (const float*)d_in[3];
    const float* Wk = (const float*)d_in[4];
    const float* bk = (const float*)d_in[5];
    const float* Wv = (const float*)d_in[6];
    const float* bv = (const float*)d_in[7];
    const float* gamma = (const float*)d_in[8];
    const float* beta  = (const float*)d_in[9];
    float* out = (float*)d_out;

    const int SM16 = 2 * 128 * 68 * 4 + 2 * 128 * 72 * 2;   // 106496
    cudaFuncSetAttribute(proj_fused_kernel, cudaFuncAttributeMaxDynamicSharedMemorySize, SM16);
    cudaFuncSetAttribute(attn_kernel, cudaFuncAttributeMaxDynamicSharedMemorySize, SMATT);

    prep_wt_kernel<<<(3 * DH * DM + 255) / 256, 256>>>(Wq, Wk, Wv);
    proj_fused_kernel<<<256, 256, SM16>>>(x1, x2, bq, bk, bv);
    xsum_combine_kernel<<<96, 256>>>();
    attn_kernel<<<dim3(16, BB), 256, SMATT>>>(bv, gamma, beta, out);
}